// round 16
// baseline (speedup 1.0000x reference)
#include <cuda_runtime.h>

#define NQ 14

struct cpx { float x, y; };

__device__ __forceinline__ cpx cmul(cpx a, cpx b) {
    return { a.x * b.x - a.y * b.y, a.x * b.y + a.y * b.x };
}
__device__ __forceinline__ cpx cadd(cpx a, cpx b) {
    return { a.x + b.x, a.y + b.y };
}
__device__ __forceinline__ void mmul2(const cpx* A, const cpx* B, cpx* C) {
    C[0] = cadd(cmul(A[0], B[0]), cmul(A[1], B[2]));
    C[1] = cadd(cmul(A[0], B[1]), cmul(A[1], B[3]));
    C[2] = cadd(cmul(A[2], B[0]), cmul(A[3], B[2]));
    C[3] = cadd(cmul(A[2], B[1]), cmul(A[3], B[3]));
}

// Fused gate G = RX(t2)*RZ(t1)*RX(t0)*RZ(x2)*RY(x1)   (validated R10-R14)
__device__ __forceinline__ void fused_gate(float xb, const float* __restrict__ th, cpx* G) {
    const float x1 = asinf(xb);
    const float x2 = acosf(xb * xb);
    float s1, c1;  sincosf(0.5f * x1, &s1, &c1);
    float sz, cz;  sincosf(0.5f * x2, &sz, &cz);
    cpx M[4] = { { cz * c1, -sz * c1 }, { -cz * s1,  sz * s1 },
                 { cz * s1,  sz * s1 }, {  cz * c1,  sz * c1 } };
    float s0, c0;   sincosf(0.5f * th[0], &s0, &c0);
    float sr1, cr1; sincosf(0.5f * th[1], &sr1, &cr1);
    float s2, c2v;  sincosf(0.5f * th[2], &s2, &c2v);
    cpx RX0[4] = { { c0, 0.f }, { 0.f, -s0 }, { 0.f, -s0 }, { c0, 0.f } };
    cpx RZ1[4] = { { cr1, -sr1 }, { 0.f, 0.f }, { 0.f, 0.f }, { cr1, sr1 } };
    cpx RX2[4] = { { c2v, 0.f }, { 0.f, -s2 }, { 0.f, -s2 }, { c2v, 0.f } };
    cpx T1[4], T2[4];
    mmul2(RX0, M,  T1);
    mmul2(RZ1, T1, T2);
    mmul2(RX2, T2, G);
}

// ============================================================================
// Transfer-matrix formulation.
//
// After folding both CNOT chains (first into the layer-0 product state via
// src = m^(m>>1), second into the parity mask 0x1555 = even bits) and dropping
// the layer-1 gates on odd bits (they provably cancel in the observable —
// validated R12-R14), the expectation factorizes over even bits:
//
//   E = sum_{odd bits o} |F13(o13)|^2 * prod_{j even} ( |u_j(0)|^2 - |u_j(1)|^2 )
//   u_j = G_j * g_j ;  g_0(e) = F0(e^o1) ;  g_j(e) = F_{j-1}(o_{j-1}^e)*F_j(e^o_{j+1})
//   F_k(s) = layer-0 fused gate of qubit 13-k, column 0, entry s
//   G_j    = layer-1 fused gate of qubit 13-j
//
// This is a chain over the 7 odd bits -> contract 6 2x2 transfer matrices.
// One warp per batch element.
// ============================================================================
__global__ __launch_bounds__(32, 1)
void qsim_tiny(const float* __restrict__ x,
               const float* __restrict__ thetas,
               float* __restrict__ out) {
    __shared__ cpx   sF[14][2];   // sF[q][s]: layer-0 gate of qubit q, col 0
    __shared__ cpx   sH[7][4];    // sH[i]: layer-1 gate of qubit 13-2i (bit 2i)
    __shared__ float sW[7][4];    // weight tables w_i[a*2+b]

    const int b    = blockIdx.x;
    const int lane = threadIdx.x;
    const float xb = x[b];

    if (lane < 14) {
        cpx G[4];
        fused_gate(xb, thetas + lane * 3, G);            // layer 0, qubit = lane
        sF[lane][0] = G[0];                              // G[0][0]
        sF[lane][1] = G[2];                              // G[1][0]
    } else if (lane < 21) {
        const int i = lane - 14;
        const int q = 13 - 2 * i;                        // qubit on even bit 2i
        cpx G[4];
        fused_gate(xb, thetas + (NQ + q) * 3, G);        // layer 1
        sH[i][0] = G[0]; sH[i][1] = G[1];
        sH[i][2] = G[2]; sH[i][3] = G[3];
    }
    __syncwarp();

    if (lane < 26) {
        int i, a, bb;
        if (lane < 2) { i = 0; a = 0; bb = lane; }
        else {
            const int idx = lane - 2;
            i  = 1 + (idx >> 2);
            a  = (idx >> 1) & 1;
            bb = idx & 1;
        }
        cpx g0, g1;
        if (i == 0) {                                    // bit 0: g(e) = Fq13[e^b]
            g0 = sF[13][bb];
            g1 = sF[13][1 ^ bb];
        } else {                                         // bit j=2i
            const int qa = 14 - 2 * i;                   // F_{j-1}: qubit 13-(2i-1)
            const int qb = 13 - 2 * i;                   // F_j    : qubit 13-2i
            g0 = cmul(sF[qa][a],     sF[qb][bb]);        // e=0
            g1 = cmul(sF[qa][a ^ 1], sF[qb][1 ^ bb]);    // e=1
        }
        const cpx h0 = sH[i][0], h1 = sH[i][1], h2 = sH[i][2], h3 = sH[i][3];
        const cpx u0 = cadd(cmul(h0, g0), cmul(h1, g1));
        const cpx u1 = cadd(cmul(h2, g0), cmul(h3, g1));
        sW[i][a * 2 + bb] = (u0.x * u0.x + u0.y * u0.y)
                          - (u1.x * u1.x + u1.y * u1.y);
    }
    __syncwarp();

    if (lane == 0) {
        float v0 = sW[0][0], v1 = sW[0][1];              // over o1
#pragma unroll
        for (int i = 1; i < 7; i++) {                    // contract o3..o13
            const float t0 = v0 * sW[i][0] + v1 * sW[i][2];
            const float t1 = v0 * sW[i][1] + v1 * sW[i][3];
            v0 = t0; v1 = t1;
        }
        const cpx f0 = sF[0][0], f1 = sF[0][1];          // tail |F13(o13)|^2
        out[b] = v0 * (f0.x * f0.x + f0.y * f0.y)
               + v1 * (f1.x * f1.x + f1.y * f1.y);
    }
}

extern "C" void kernel_launch(void* const* d_in, const int* in_sizes, int n_in,
                              void* d_out, int out_size) {
    const float* x      = (const float*)d_in[0];
    const float* thetas = (const float*)d_in[1];
    float* out          = (float*)d_out;
    qsim_tiny<<<64, 32>>>(x, thetas, out);
}

// round 17
// speedup vs baseline: 1.0435x; 1.0435x over previous
#include <cuda_runtime.h>

#define NQ 14

struct cpx { float x, y; };

__device__ __forceinline__ cpx cmul(cpx a, cpx b) {
    return { a.x * b.x - a.y * b.y, a.x * b.y + a.y * b.x };
}
__device__ __forceinline__ cpx cadd(cpx a, cpx b) {
    return { a.x + b.x, a.y + b.y };
}
__device__ __forceinline__ void mmul2(const cpx* A, const cpx* B, cpx* C) {
    C[0] = cadd(cmul(A[0], B[0]), cmul(A[1], B[2]));
    C[1] = cadd(cmul(A[0], B[1]), cmul(A[1], B[3]));
    C[2] = cadd(cmul(A[2], B[0]), cmul(A[3], B[2]));
    C[3] = cadd(cmul(A[2], B[1]), cmul(A[3], B[3]));
}

// Fused gate G = RX(t2)*RZ(t1)*RX(t0)*RZ(x2)*RY(x1).
// Feature-map half-angle trig done with sqrt identities (x in [0,1)):
//   x1 = asin(x):  cos(x1)=sqrt(1-x^2), c1=sqrt((1+cos x1)/2), s1=x/(2 c1)
//   x2 = acos(x^2): cz=sqrt((1+x^2)/2), sz=sqrt((1-x^2)/2)
__device__ __forceinline__ void fused_gate_fast(float xb, const float* __restrict__ th,
                                                cpx* G) {
    const float x2c = xb * xb;
    const float cx1 = sqrtf(fmaxf(1.0f - x2c, 0.0f));   // cos(asin x)
    const float c1  = sqrtf(0.5f * (1.0f + cx1));
    const float s1  = 0.5f * xb / c1;
    const float cz  = sqrtf(0.5f * (1.0f + x2c));
    const float sz  = sqrtf(fmaxf(0.5f * (1.0f - x2c), 0.0f));

    cpx M[4] = { { cz * c1, -sz * c1 }, { -cz * s1,  sz * s1 },
                 { cz * s1,  sz * s1 }, {  cz * c1,  sz * c1 } };

    float s0, c0;   sincosf(0.5f * th[0], &s0, &c0);
    float sr1, cr1; sincosf(0.5f * th[1], &sr1, &cr1);
    float s2, c2v;  sincosf(0.5f * th[2], &s2, &c2v);

    cpx RX0[4] = { { c0, 0.f }, { 0.f, -s0 }, { 0.f, -s0 }, { c0, 0.f } };
    cpx RZ1[4] = { { cr1, -sr1 }, { 0.f, 0.f }, { 0.f, 0.f }, { cr1, sr1 } };
    cpx RX2[4] = { { c2v, 0.f }, { 0.f, -s2 }, { 0.f, -s2 }, { c2v, 0.f } };
    cpx T1[4], T2[4];
    mmul2(RX0, M,  T1);
    mmul2(RZ1, T1, T2);
    mmul2(RX2, T2, G);
}

// ============================================================================
// Transfer-matrix contraction (derivation validated R14/R16):
//   E = sum_{odd o} |F13(o13)|^2 * prod_{j even} (|u_j(0)|^2 - |u_j(1)|^2)
//   u_j = G_j * g_j ; g_0(e)=F0(e^o1) ; g_j(e)=F_{j-1}(o_{j-1}^e)*F_j(e^o_{j+1})
// One warp per batch element; all 21 gate computations run in ONE non-divergent
// fused_gate call (divergence only at the store).
// ============================================================================
__global__ __launch_bounds__(32, 1)
void qsim_tiny(const float* __restrict__ x,
               const float* __restrict__ thetas,
               float* __restrict__ out) {
    __shared__ cpx   sF[14][2];   // layer-0 gate of qubit q, column 0
    __shared__ cpx   sH[7][4];    // layer-1 gate on even bit 2i (qubit 13-2i)
    __shared__ float sW[7][4];    // weight tables w_i[a*2+b]

    const int b    = blockIdx.x;
    const int lane = threadIdx.x;
    const float xb = x[b];

    if (lane < 21) {
        // unified theta index: layer 0 qubit=lane; layer 1 qubit=13-2*(lane-14)
        const int ti = (lane < 14) ? lane : (NQ + 13 - 2 * (lane - 14));
        cpx G[4];
        fused_gate_fast(xb, thetas + ti * 3, G);
        if (lane < 14) {
            sF[lane][0] = G[0];          // column 0
            sF[lane][1] = G[2];
        } else {
            const int i = lane - 14;
            sH[i][0] = G[0]; sH[i][1] = G[1];
            sH[i][2] = G[2]; sH[i][3] = G[3];
        }
    }
    __syncwarp();

    if (lane < 26) {
        int i, a, bb;
        if (lane < 2) { i = 0; a = 0; bb = lane; }
        else {
            const int idx = lane - 2;
            i  = 1 + (idx >> 2);
            a  = (idx >> 1) & 1;
            bb = idx & 1;
        }
        cpx g0, g1;
        if (i == 0) {                                    // bit 0: g(e) = F_q13[e^b]
            g0 = sF[13][bb];
            g1 = sF[13][1 ^ bb];
        } else {                                         // bit j = 2i
            const int qa = 14 - 2 * i;                   // F_{j-1}: qubit 13-(2i-1)
            const int qb = 13 - 2 * i;                   // F_j    : qubit 13-2i
            g0 = cmul(sF[qa][a],     sF[qb][bb]);        // e=0
            g1 = cmul(sF[qa][a ^ 1], sF[qb][1 ^ bb]);    // e=1
        }
        const cpx h0 = sH[i][0], h1 = sH[i][1], h2 = sH[i][2], h3 = sH[i][3];
        const cpx u0 = cadd(cmul(h0, g0), cmul(h1, g1));
        const cpx u1 = cadd(cmul(h2, g0), cmul(h3, g1));
        sW[i][a * 2 + bb] = (u0.x * u0.x + u0.y * u0.y)
                          - (u1.x * u1.x + u1.y * u1.y);
    }
    __syncwarp();

    if (lane == 0) {
        float v0 = sW[0][0], v1 = sW[0][1];              // over o1
#pragma unroll
        for (int i = 1; i < 7; i++) {                    // contract o3..o13
            const float t0 = v0 * sW[i][0] + v1 * sW[i][2];
            const float t1 = v0 * sW[i][1] + v1 * sW[i][3];
            v0 = t0; v1 = t1;
        }
        const cpx f0 = sF[0][0], f1 = sF[0][1];          // tail |F13(o13)|^2
        out[b] = v0 * (f0.x * f0.x + f0.y * f0.y)
               + v1 * (f1.x * f1.x + f1.y * f1.y);
    }
}

extern "C" void kernel_launch(void* const* d_in, const int* in_sizes, int n_in,
                              void* d_out, int out_size) {
    const float* x      = (const float*)d_in[0];
    const float* thetas = (const float*)d_in[1];
    float* out          = (float*)d_out;
    qsim_tiny<<<64, 32>>>(x, thetas, out);
}